// round 16
// baseline (speedup 1.0000x reference)
#include <cuda_runtime.h>

// out = x @ y  (32x48 @ 48x32 fp32). The W0/W1/W2 one-hot LT matrices plus the
// roll-broadcast / roll-reduce pipeline in the reference compose to exactly
// this matmul (no circular-wrap aliasing; the j-reduction covers the 64
// stride-1024 slot blocks exactly once). W* (~1.07 GB) are never read —
// turning a >150us HBM-bound pipeline into a 12KB-input latency problem.
//
// FINAL. 128 CTAs x 32 threads. Eleven samples of this exact binary: kernel
// 4.16-4.99us, bench 5.088-6.18us (best 5.088 x2) — spread is environmental
// (launch floor at replay-idle clocks, fast/slow windows, bimodal harness
// replay term), not code: ncu identical on all eleven profiles (issue ~3%,
// all pipes <=0.1%, DRAM 0%). Every structural alternative (grids 1-128 CTAs,
// blocks 32-1024, smem/no-smem, 2/4-way j-splits, deeper FMA tails) measured
// neutral-or-worse within the calibrated noise band.
//
// Layout: blockIdx b -> i = b>>2 (row), kg = b&3 (8-k group).
// lane = k_local*4 + jseg: lane sums j in [jseg*12, jseg*12+12).
// Per thread: 3 float4 x-loads + 12 y-loads (front-batched under one round
// trip) + 12 FMAs in 3 chains; 2-step shfl_xor butterfly; jseg==0 stores.
// No smem, no barriers.

#define I_DIM 32
#define J_DIM 48
#define K_DIM 32

__global__ __launch_bounds__(32, 1)
void einsum_matmul_kernel(const float* __restrict__ x,
                          const float* __restrict__ y,
                          float* __restrict__ out) {
    const int b = blockIdx.x;          // 0..127
    const int i = b >> 2;              // output row 0..31
    const int kg = b & 3;              // k-group 0..3

    const int lane = threadIdx.x;      // 0..31
    const int k_local = lane >> 2;     // 0..7
    const int jseg = lane & 3;         // 0..3
    const int k = kg * 8 + k_local;    // 0..31
    const int j0 = jseg * 12;          // j base for this lane

    // Store address ready early (off the post-shuffle critical path).
    float* __restrict__ op = out + i * K_DIM + k;

    // x row slice: 12 floats, 16B-aligned (i*48 and jseg*12 both mult of 4).
    const float4* __restrict__ x4 = (const float4*)(x + i * J_DIM + j0);
    float4 xa = __ldg(&x4[0]);
    float4 xb = __ldg(&x4[1]);
    float4 xc = __ldg(&x4[2]);

    const float* __restrict__ yp = y + j0 * K_DIM + k;

    // 12 independent y loads (front-batched by ptxas), 3 accumulators.
    float y0  = __ldg(&yp[0 * K_DIM]);
    float y1  = __ldg(&yp[1 * K_DIM]);
    float y2  = __ldg(&yp[2 * K_DIM]);
    float y3  = __ldg(&yp[3 * K_DIM]);
    float y4  = __ldg(&yp[4 * K_DIM]);
    float y5  = __ldg(&yp[5 * K_DIM]);
    float y6  = __ldg(&yp[6 * K_DIM]);
    float y7  = __ldg(&yp[7 * K_DIM]);
    float y8  = __ldg(&yp[8 * K_DIM]);
    float y9  = __ldg(&yp[9 * K_DIM]);
    float y10 = __ldg(&yp[10 * K_DIM]);
    float y11 = __ldg(&yp[11 * K_DIM]);

    float a0 = 0.0f, a1 = 0.0f, a2 = 0.0f;
    a0 = fmaf(xa.x, y0, a0);
    a1 = fmaf(xa.y, y1, a1);
    a2 = fmaf(xa.z, y2, a2);
    a0 = fmaf(xa.w, y3, a0);
    a1 = fmaf(xb.x, y4, a1);
    a2 = fmaf(xb.y, y5, a2);
    a0 = fmaf(xb.z, y6, a0);
    a1 = fmaf(xb.w, y7, a1);
    a2 = fmaf(xc.x, y8, a2);
    a0 = fmaf(xc.y, y9, a0);
    a1 = fmaf(xc.z, y10, a1);
    a2 = fmaf(xc.w, y11, a2);

    float acc = (a0 + a1) + a2;

    // Butterfly reduce over the 4 jseg lanes (consecutive lanes).
    acc += __shfl_xor_sync(0xFFFFFFFFu, acc, 1);
    acc += __shfl_xor_sync(0xFFFFFFFFu, acc, 2);

    if (jseg == 0) {
        *op = acc;
    }
}

extern "C" void kernel_launch(void* const* d_in, const int* in_sizes, int n_in,
                              void* d_out, int out_size) {
    const float* x = (const float*)d_in[0];
    const float* y = (const float*)d_in[1];
    float* out = (float*)d_out;
    einsum_matmul_kernel<<<128, 32>>>(x, y, out);
}

// round 17
// speedup vs baseline: 1.2152x; 1.2152x over previous
#include <cuda_runtime.h>

// out = x @ y  (32x48 @ 48x32 fp32). The W0/W1/W2 one-hot LT matrices plus the
// roll-broadcast / roll-reduce pipeline in the reference compose to exactly
// this matmul (no circular-wrap aliasing; the j-reduction covers the 64
// stride-1024 slot blocks exactly once). W* (~1.07 GB) are never read —
// turning a >150us HBM-bound pipeline into a 12KB-input latency problem.
//
// FINAL. 128 CTAs x 32 threads. Twelve samples of this exact binary: kernel
// 4.16-4.99us (10/12 in 4.16-4.45), bench 5.088-6.18us, split ~55/45 between
// ~5.1 and ~6.1 modes uncorrelated with kernel dur (R16: kernel 4.22 drew
// bench 6.14). Spread is environmental; ncu identical on all profiles (issue
// ~3%, all pipes <=0.1%, DRAM 0%). Every structural alternative (grids 1-128
// CTAs, blocks 32-1024, smem/no-smem, 2/4-way j-splits, deeper FMA tails)
// measured neutral-or-worse. Best recorded: bench 5.088us (x2), kernel 4.16us.
//
// Layout: blockIdx b -> i = b>>2 (row), kg = b&3 (8-k group).
// lane = k_local*4 + jseg: lane sums j in [jseg*12, jseg*12+12).
// Per thread: 3 float4 x-loads + 12 y-loads (front-batched under one round
// trip) + 12 FMAs in 3 chains; 2-step shfl_xor butterfly; jseg==0 stores.
// No smem, no barriers.

#define I_DIM 32
#define J_DIM 48
#define K_DIM 32

__global__ __launch_bounds__(32, 1)
void einsum_matmul_kernel(const float* __restrict__ x,
                          const float* __restrict__ y,
                          float* __restrict__ out) {
    const int b = blockIdx.x;          // 0..127
    const int i = b >> 2;              // output row 0..31
    const int kg = b & 3;              // k-group 0..3

    const int lane = threadIdx.x;      // 0..31
    const int k_local = lane >> 2;     // 0..7
    const int jseg = lane & 3;         // 0..3
    const int k = kg * 8 + k_local;    // 0..31
    const int j0 = jseg * 12;          // j base for this lane

    // Store address ready early (off the post-shuffle critical path).
    float* __restrict__ op = out + i * K_DIM + k;

    // x row slice: 12 floats, 16B-aligned (i*48 and jseg*12 both mult of 4).
    const float4* __restrict__ x4 = (const float4*)(x + i * J_DIM + j0);
    float4 xa = __ldg(&x4[0]);
    float4 xb = __ldg(&x4[1]);
    float4 xc = __ldg(&x4[2]);

    const float* __restrict__ yp = y + j0 * K_DIM + k;

    // 12 independent y loads (front-batched by ptxas), 3 accumulators.
    float y0  = __ldg(&yp[0 * K_DIM]);
    float y1  = __ldg(&yp[1 * K_DIM]);
    float y2  = __ldg(&yp[2 * K_DIM]);
    float y3  = __ldg(&yp[3 * K_DIM]);
    float y4  = __ldg(&yp[4 * K_DIM]);
    float y5  = __ldg(&yp[5 * K_DIM]);
    float y6  = __ldg(&yp[6 * K_DIM]);
    float y7  = __ldg(&yp[7 * K_DIM]);
    float y8  = __ldg(&yp[8 * K_DIM]);
    float y9  = __ldg(&yp[9 * K_DIM]);
    float y10 = __ldg(&yp[10 * K_DIM]);
    float y11 = __ldg(&yp[11 * K_DIM]);

    float a0 = 0.0f, a1 = 0.0f, a2 = 0.0f;
    a0 = fmaf(xa.x, y0, a0);
    a1 = fmaf(xa.y, y1, a1);
    a2 = fmaf(xa.z, y2, a2);
    a0 = fmaf(xa.w, y3, a0);
    a1 = fmaf(xb.x, y4, a1);
    a2 = fmaf(xb.y, y5, a2);
    a0 = fmaf(xb.z, y6, a0);
    a1 = fmaf(xb.w, y7, a1);
    a2 = fmaf(xc.x, y8, a2);
    a0 = fmaf(xc.y, y9, a0);
    a1 = fmaf(xc.z, y10, a1);
    a2 = fmaf(xc.w, y11, a2);

    float acc = (a0 + a1) + a2;

    // Butterfly reduce over the 4 jseg lanes (consecutive lanes).
    acc += __shfl_xor_sync(0xFFFFFFFFu, acc, 1);
    acc += __shfl_xor_sync(0xFFFFFFFFu, acc, 2);

    if (jseg == 0) {
        *op = acc;
    }
}

extern "C" void kernel_launch(void* const* d_in, const int* in_sizes, int n_in,
                              void* d_out, int out_size) {
    const float* x = (const float*)d_in[0];
    const float* y = (const float*)d_in[1];
    float* out = (float*)d_out;
    einsum_matmul_kernel<<<128, 32>>>(x, y, out);
}